// round 6
// baseline (speedup 1.0000x reference)
#include <cuda_runtime.h>

#define BATCH 8
#define CH    512
#define HW    4096
#define NMASK 1024
#define NCTX  3072
#define EPSF  1e-8f
#define NSPLIT 4

// ---------------- scratch (static __device__ globals; no allocation) ----------
__device__ float g_Am[BATCH * CH * NMASK];            // A gathered [b][k][i]
__device__ float g_Bn[BATCH * CH * NCTX];             // B gathered [b][k][j]
__device__ float g_best[BATCH * NMASK * CH];
__device__ float g_mskn[BATCH * NMASK * CH];
__device__ float g_gen[BATCH * NMASK * CH];
__device__ float g_part[NSPLIT][BATCH * HW];
__device__ float g_invall[BATCH * HW];
__device__ float g_invc[BATCH * NCTX];
__device__ float g_invm[BATCH * NMASK];
__device__ float g_maxc[BATCH * NMASK];
__device__ unsigned long long g_packed[BATCH * NMASK];
__device__ int   g_imask[HW];

// ---------------- K1a: partial column norms ---------------------------------
__global__ void k_part(const float* __restrict__ x) {
    int p = blockIdx.x * 256 + threadIdx.x;
    int b = blockIdx.y;
    int z = blockIdx.z;
    const float* base = x + ((size_t)b * CH + (size_t)z * (CH / NSPLIT)) * HW + p;
    float s = 0.f;
#pragma unroll 8
    for (int c = 0; c < CH / NSPLIT; c++) {
        float v = base[(size_t)c * HW];
        s += v * v;
    }
    g_part[z][b * HW + p] = s;
}

// ---------------- K1b: combine partials -> invall ---------------------------
__global__ void k_invall() {
    int i = blockIdx.x * 256 + threadIdx.x;
    float s = g_part[0][i] + g_part[1][i] + g_part[2][i] + g_part[3][i];
    g_invall[i] = 1.f / (sqrtf(s) + EPSF);
}

// ---------------- K2: setup --------------------------------------------------
__global__ void k_setup(const int* __restrict__ np, const int* __restrict__ mp) {
    int t = threadIdx.x;  // 1024 threads, 1 block
    for (int p = t; p < HW; p += 1024) g_imask[p] = -1;
    __syncthreads();
    g_imask[mp[t]] = t;
    for (int i = t; i < BATCH * NMASK; i += 1024) g_packed[i] = 0ull;
    for (int i = t; i < BATCH * NMASK; i += 1024) {
        int b = i / NMASK;
        g_invm[i] = g_invall[b * HW + mp[i % NMASK]];
    }
    for (int j = t; j < BATCH * NCTX; j += 1024) {
        int b = j / NCTX;
        g_invc[j] = g_invall[b * HW + np[j % NCTX]];
    }
}

// ---------------- K3: gather A (mask cols) and B (ctx cols), K-major --------
__global__ void k_gather(const float* __restrict__ x,
                         const int* __restrict__ np, const int* __restrict__ mp) {
    int k = blockIdx.x;
    int b = blockIdx.y;
    int t = threadIdx.x;        // 1024
    const float* row = x + ((size_t)b * CH + k) * HW;
    g_Am[((size_t)b * CH + k) * NMASK + t] = row[mp[t]];
#pragma unroll
    for (int j = t; j < NCTX; j += 1024)
        g_Bn[((size_t)b * CH + k) * NCTX + j] = row[np[j]];
}

// ---------------- K4: fp32 GEMM (cp.async pipeline, f32x2 FFMA) -------------
#define BM 128
#define BN 128
#define BK 16
#define NT (CH / BK)

__device__ __forceinline__ unsigned ford(float f) {
    unsigned u = __float_as_uint(f);
    return (u & 0x80000000u) ? ~u : (u | 0x80000000u);
}

__device__ __forceinline__ void cp16(void* sdst, const void* gsrc) {
    unsigned saddr = (unsigned)__cvta_generic_to_shared(sdst);
    asm volatile("cp.async.ca.shared.global [%0], [%1], 16;\n" :: "r"(saddr), "l"(gsrc));
}

__global__ void __launch_bounds__(256, 2) k_gemm() {
    __shared__ __align__(16) float As[2][BK][BM];
    __shared__ __align__(16) float Bs[2][BK][BN];

    int b  = blockIdx.z;
    int i0 = blockIdx.y * BM;
    int j0 = blockIdx.x * BN;
    int tid = threadIdx.x;
    int tx = tid & 15, ty = tid >> 4;
    int cA = tx * 4;

    const float* A  = g_Am + (size_t)b * CH * NMASK + i0;
    const float* Bp = g_Bn + (size_t)b * CH * NCTX  + j0;

    unsigned long long acc[8][4];
#pragma unroll
    for (int r = 0; r < 8; r++)
#pragma unroll
        for (int q = 0; q < 4; q++) acc[r][q] = 0ull;

#define COPY_TILE(t)                                                          \
    do {                                                                      \
        int s_ = (t) & 1;                                                     \
        const float* ga = A  + (size_t)((t) * BK + ty) * NMASK + cA;          \
        const float* gb = Bp + (size_t)((t) * BK + ty) * NCTX  + cA;          \
        cp16(&As[s_][ty][cA],      ga);                                       \
        cp16(&As[s_][ty][64 + cA], ga + 64);                                  \
        cp16(&Bs[s_][ty][cA],      gb);                                       \
        cp16(&Bs[s_][ty][64 + cA], gb + 64);                                  \
        asm volatile("cp.async.commit_group;\n");                             \
    } while (0)

    COPY_TILE(0);
    COPY_TILE(1);

#pragma unroll 1
    for (int t = 0; t < NT; t++) {
        if (t < NT - 1) asm volatile("cp.async.wait_group 1;\n");
        else            asm volatile("cp.async.wait_group 0;\n");
        __syncthreads();
        int s = t & 1;
#pragma unroll
        for (int kk = 0; kk < BK; kk++) {
            float4 a0 = *(const float4*)&As[s][kk][ty * 4];
            float4 a1 = *(const float4*)&As[s][kk][64 + ty * 4];
            ulonglong2 bv0 = *(const ulonglong2*)&Bs[s][kk][tx * 4];
            ulonglong2 bv1 = *(const ulonglong2*)&Bs[s][kk][64 + tx * 4];
            float ar[8] = {a0.x, a0.y, a0.z, a0.w, a1.x, a1.y, a1.z, a1.w};
            unsigned long long bq[4] = {bv0.x, bv0.y, bv1.x, bv1.y};
#pragma unroll
            for (int r = 0; r < 8; r++) {
                unsigned long long a2;
                asm("mov.b64 %0, {%1, %1};" : "=l"(a2) : "r"(__float_as_uint(ar[r])));
#pragma unroll
                for (int q = 0; q < 4; q++)
                    asm("fma.rn.f32x2 %0, %1, %2, %0;"
                        : "+l"(acc[r][q]) : "l"(a2), "l"(bq[q]));
            }
        }
        __syncthreads();
        if (t + 2 < NT) COPY_TILE(t + 2);
    }

    float invc[8];
#pragma unroll
    for (int g = 0; g < 2; g++)
#pragma unroll
        for (int e = 0; e < 4; e++)
            invc[g * 4 + e] = g_invc[b * NCTX + j0 + g * 64 + tx * 4 + e];

#pragma unroll
    for (int r = 0; r < 8; r++) {
        int irow = (r < 4) ? (ty * 4 + r) : (64 + ty * 4 + (r - 4));
        unsigned long long bp = 0ull;
#pragma unroll
        for (int q = 0; q < 4; q++) {
            float lo = __uint_as_float((unsigned)acc[r][q]);
            float hi = __uint_as_float((unsigned)(acc[r][q] >> 32));
            float v0 = lo * invc[q * 2];
            float v1 = hi * invc[q * 2 + 1];
            int jg = j0 + ((q >> 1) * 64) + tx * 4 + (q & 1) * 2;
            unsigned long long p0 = ((unsigned long long)ford(v0) << 32) | (unsigned)(~(unsigned)jg);
            unsigned long long p1 = ((unsigned long long)ford(v1) << 32) | (unsigned)(~(unsigned)(jg + 1));
            if (p0 > bp) bp = p0;
            if (p1 > bp) bp = p1;
        }
#pragma unroll
        for (int o = 1; o < 16; o <<= 1) {
            unsigned long long other = __shfl_xor_sync(0xffffffffu, bp, o);
            if (other > bp) bp = other;
        }
        if (tx == 0) atomicMax(&g_packed[b * NMASK + i0 + irow], bp);
    }
}

// ---------------- K5: finalize pick + gather from L2-hot scratch ------------
__global__ void k_finalize() {
    int i = blockIdx.x;
    int b = blockIdx.y;
    int t = threadIdx.x;  // 256
    __shared__ int s_j;
    __shared__ float s_invm;
    if (t == 0) {
        unsigned long long pk = g_packed[b * NMASK + i];
        unsigned j  = ~(unsigned)pk;
        unsigned ov = (unsigned)(pk >> 32);
        unsigned fb = (ov & 0x80000000u) ? (ov & 0x7fffffffu) : ~ov;
        float val = __uint_as_float(fb);
        float im  = g_invm[b * NMASK + i];
        g_maxc[b * NMASK + i] = val * im;
        s_j = (int)j;
        s_invm = im;
    }
    __syncthreads();
    int jj = s_j;
    float im = s_invm;
    const float* Am = g_Am + (size_t)b * CH * NMASK;
    const float* Bn = g_Bn + (size_t)b * CH * NCTX;
    size_t o = ((size_t)b * NMASK + i) * CH;
#pragma unroll
    for (int c = t; c < CH; c += 256) {
        g_best[o + c] = Bn[(size_t)c * NCTX + jj];
        g_mskn[o + c] = Am[(size_t)c * NMASK + i] * im;
    }
}

// ---------------- K6: warp-specialized sequential scan ----------------------
// warp 0 = consumer (dependent math chain only)
// warp 1 = producer (cp.async prefetch ring + GE writeback)
#define NSTAGE 8

__device__ __forceinline__ float frcp(float x) {
    float r;
    asm("rcp.approx.f32 %0, %1;" : "=f"(r) : "f"(x));
    return r;
}
__device__ __forceinline__ float frsq(float x) {
    float r;
    asm("rsqrt.approx.f32 %0, %1;" : "=f"(r) : "f"(x));
    return r;
}
__device__ __forceinline__ void st_release_s32(volatile int* p, int v) {
    unsigned a = (unsigned)__cvta_generic_to_shared((void*)p);
    asm volatile("st.release.cta.shared.b32 [%0], %1;" :: "r"(a), "r"(v) : "memory");
}
__device__ __forceinline__ int ld_acquire_s32(volatile int* p) {
    unsigned a = (unsigned)__cvta_generic_to_shared((void*)p);
    int v;
    asm volatile("ld.acquire.cta.shared.b32 %0, [%1];" : "=r"(v) : "r"(a) : "memory");
    return v;
}

__global__ void __launch_bounds__(64, 1) k_scan() {
    __shared__ __align__(16) float ring[NSTAGE][2][CH];   // 32KB operand ring
    __shared__ __align__(16) float qbuf[NSTAGE][CH];      // 16KB q ring
    __shared__ int rflag[NSTAGE];                         // slot -> step ready
    __shared__ int qflag[NSTAGE];                         // slot -> q ready

    int b = blockIdx.x;
    int warp = threadIdx.x >> 5;
    int lane = threadIdx.x & 31;

    const float* MN = g_mskn + (size_t)b * NMASK * CH;
    const float* BS = g_best + (size_t)b * NMASK * CH;
    float*       GE = g_gen  + (size_t)b * NMASK * CH;
    const float* MX = g_maxc + b * NMASK;
    size_t lo = (size_t)lane * 16;

    if (threadIdx.x < NSTAGE) { rflag[threadIdx.x] = -1; qflag[threadIdx.x] = -1; }
    __syncthreads();

#define SCAN_PREFETCH(i, s)                                                   \
    do {                                                                      \
        const float* pm = MN + (size_t)(i) * CH + lo;                         \
        const float* pb = BS + (size_t)(i) * CH + lo;                         \
        cp16(&ring[s][0][lo],      pm);                                       \
        cp16(&ring[s][0][lo + 4],  pm + 4);                                   \
        cp16(&ring[s][0][lo + 8],  pm + 8);                                   \
        cp16(&ring[s][0][lo + 12], pm + 12);                                  \
        cp16(&ring[s][1][lo],      pb);                                       \
        cp16(&ring[s][1][lo + 4],  pb + 4);                                   \
        cp16(&ring[s][1][lo + 8],  pb + 8);                                   \
        cp16(&ring[s][1][lo + 12], pb + 12);                                  \
        asm volatile("cp.async.commit_group;\n");                             \
    } while (0)

    if (warp == 1) {
        // ---------------- producer ----------------
#pragma unroll
        for (int s = 0; s < NSTAGE; s++) SCAN_PREFETCH(s, s);
        // step 0 ready
        asm volatile("cp.async.wait_group %0;\n" :: "n"(NSTAGE - 1));
        __threadfence_block();
        if (lane == 0) st_release_s32(&rflag[0], 0);

#pragma unroll 1
        for (int i = 0; i < NMASK; i++) {
            int s = i & (NSTAGE - 1);
            // wait for consumer's q of step i
            while (ld_acquire_s32(&qflag[s]) < i) { }
            // write GE[i]
            float* ge = GE + (size_t)i * CH + lo;
#pragma unroll
            for (int u = 0; u < 4; u++)
                *(float4*)(ge + u * 4) = *(const float4*)&qbuf[s][lo + u * 4];
            // recycle slot s for step i+NSTAGE
            if (i + NSTAGE < NMASK) SCAN_PREFETCH(i + NSTAGE, s);
            else asm volatile("cp.async.commit_group;\n");
            // step i+1's group now completes at <= NSTAGE-1 outstanding
            if (i + 1 < NMASK) {
                asm volatile("cp.async.wait_group %0;\n" :: "n"(NSTAGE - 1));
                __threadfence_block();
                if (lane == 0) st_release_s32(&rflag[(i + 1) & (NSTAGE - 1)], i + 1);
            }
        }
    } else {
        // ---------------- consumer ----------------
        float q[16];
#pragma unroll
        for (int e = 0; e < 16; e++) q[e] = 0.f;
        float mx0 = MX[0];

#pragma unroll 1
        for (int i = 0; i < NMASK; i++) {
            int s = i & (NSTAGE - 1);
            float mx = mx0;
            mx0 = (i + 1 < NMASK) ? MX[i + 1] : 0.f;

            while (ld_acquire_s32(&rflag[s]) < i) { }

            float mn[16], bs[16];
#pragma unroll
            for (int u = 0; u < 4; u++) {
                float4 a = *(const float4*)&ring[s][0][lo + u * 4];
                mn[u * 4 + 0] = a.x; mn[u * 4 + 1] = a.y; mn[u * 4 + 2] = a.z; mn[u * 4 + 3] = a.w;
                float4 c = *(const float4*)&ring[s][1][lo + u * 4];
                bs[u * 4 + 0] = c.x; bs[u * 4 + 1] = c.y; bs[u * 4 + 2] = c.z; bs[u * 4 + 3] = c.w;
            }

            float p1[8], p2[8];
#pragma unroll
            for (int e = 0; e < 8; e++) {
                p1[e] = __fmaf_rn(q[e], q[e], q[e + 8] * q[e + 8]);
                p2[e] = __fmaf_rn(mn[e], q[e], mn[e + 8] * q[e + 8]);
            }
#pragma unroll
            for (int w = 4; w; w >>= 1)
#pragma unroll
                for (int e = 0; e < w; e++) { p1[e] += p1[e + w]; p2[e] += p2[e + w]; }
            float s1 = p1[0], s2 = p2[0];
#pragma unroll
            for (int o = 16; o; o >>= 1) {
                s1 += __shfl_xor_sync(0xffffffffu, s1, o);
                s2 += __shfl_xor_sync(0xffffffffu, s2, o);
            }
            float r   = (s1 > 0.f) ? frsq(s1) : 0.f;
            float nrm = s1 * r;                          // sqrt(s1), 0 if s1==0
            float u   = __fmaf_rn(mx, nrm, mx * EPSF);   // mx*(nrm+eps)
            float s2p = fmaxf(s2, 0.f);
            float T   = __fmaf_rn(EPSF, nrm, s2p + u);
            float rT  = frcp(T);
            float w1 = s2p * rT, w2 = u * rT;
#pragma unroll
            for (int e = 0; e < 16; e++) q[e] = __fmaf_rn(w1, q[e], w2 * bs[e]);

            // publish q for producer writeback
#pragma unroll
            for (int u = 0; u < 4; u++) {
                float4 w;
                w.x = q[u * 4 + 0]; w.y = q[u * 4 + 1]; w.z = q[u * 4 + 2]; w.w = q[u * 4 + 3];
                *(float4*)&qbuf[s][lo + u * 4] = w;
            }
            if (lane == 0) st_release_s32(&qflag[s], i);
            __syncwarp();
        }
    }
}

// ---------------- K7: assemble output ---------------------------------------
__global__ void k_out(const float* __restrict__ x, float* __restrict__ out) {
    int idx = blockIdx.x * 256 + threadIdx.x;
    int p = idx & (HW - 1);
    int c = (idx >> 12) & (CH - 1);
    int b = idx >> 21;
    int mi = g_imask[p];
    float v = (mi >= 0) ? g_gen[(((size_t)b * NMASK) + mi) * CH + c] : x[idx];
    out[idx] = v;
}

// ---------------- launch -----------------------------------------------------
extern "C" void kernel_launch(void* const* d_in, const int* in_sizes, int n_in,
                              void* d_out, int out_size) {
    const float* x  = (const float*)d_in[0];
    const int*   np = (const int*)d_in[2];
    const int*   mp = (const int*)d_in[3];
    float*       out = (float*)d_out;

    k_part    <<<dim3(HW / 256, BATCH, NSPLIT), 256>>>(x);
    k_invall  <<<BATCH * HW / 256, 256>>>();
    k_setup   <<<1, 1024>>>(np, mp);
    k_gather  <<<dim3(CH, BATCH), 1024>>>(x, np, mp);
    k_gemm    <<<dim3(NCTX / BN, NMASK / BM, BATCH), 256>>>();
    k_finalize<<<dim3(NMASK, BATCH), 256>>>();
    k_scan    <<<BATCH, 64>>>();
    k_out     <<<(BATCH * CH * HW) / 256, 256>>>(x, out);
}

// round 7
// speedup vs baseline: 1.2024x; 1.2024x over previous
#include <cuda_runtime.h>

#define BATCH 8
#define CH    512
#define HW    4096
#define NMASK 1024
#define NCTX  3072
#define EPSF  1e-8f
#define NSPLIT 4

// ---------------- scratch (static __device__ globals; no allocation) ----------
__device__ float g_Am[BATCH * CH * NMASK];            // A gathered [b][k][i]
__device__ float g_Bn[BATCH * CH * NCTX];             // B gathered [b][k][j]
__device__ float g_best[BATCH * NMASK * CH];
__device__ float g_mskn[BATCH * NMASK * CH];
__device__ float g_gen[BATCH * NMASK * CH];
__device__ float g_part[NSPLIT][BATCH * HW];
__device__ float g_invall[BATCH * HW];
__device__ float g_invc[BATCH * NCTX];
__device__ float g_invm[BATCH * NMASK];
__device__ float g_maxc[BATCH * NMASK];
__device__ unsigned long long g_packed[BATCH * NMASK];
__device__ int   g_imask[HW];

// ---------------- K1a: partial column norms ---------------------------------
__global__ void k_part(const float* __restrict__ x) {
    int p = blockIdx.x * 256 + threadIdx.x;
    int b = blockIdx.y;
    int z = blockIdx.z;
    const float* base = x + ((size_t)b * CH + (size_t)z * (CH / NSPLIT)) * HW + p;
    float s = 0.f;
#pragma unroll 8
    for (int c = 0; c < CH / NSPLIT; c++) {
        float v = base[(size_t)c * HW];
        s += v * v;
    }
    g_part[z][b * HW + p] = s;
}

// ---------------- K1b: combine partials -> invall ---------------------------
__global__ void k_invall() {
    int i = blockIdx.x * 256 + threadIdx.x;
    float s = g_part[0][i] + g_part[1][i] + g_part[2][i] + g_part[3][i];
    g_invall[i] = 1.f / (sqrtf(s) + EPSF);
}

// ---------------- K2: setup --------------------------------------------------
__global__ void k_setup(const int* __restrict__ np, const int* __restrict__ mp) {
    int t = threadIdx.x;  // 1024 threads, 1 block
    for (int p = t; p < HW; p += 1024) g_imask[p] = -1;
    __syncthreads();
    g_imask[mp[t]] = t;
    for (int i = t; i < BATCH * NMASK; i += 1024) g_packed[i] = 0ull;
    for (int i = t; i < BATCH * NMASK; i += 1024) {
        int b = i / NMASK;
        g_invm[i] = g_invall[b * HW + mp[i % NMASK]];
    }
    for (int j = t; j < BATCH * NCTX; j += 1024) {
        int b = j / NCTX;
        g_invc[j] = g_invall[b * HW + np[j % NCTX]];
    }
}

// ---------------- K3: gather A (mask cols) and B (ctx cols), K-major --------
__global__ void k_gather(const float* __restrict__ x,
                         const int* __restrict__ np, const int* __restrict__ mp) {
    int k = blockIdx.x;
    int b = blockIdx.y;
    int t = threadIdx.x;        // 1024
    const float* row = x + ((size_t)b * CH + k) * HW;
    g_Am[((size_t)b * CH + k) * NMASK + t] = row[mp[t]];
#pragma unroll
    for (int j = t; j < NCTX; j += 1024)
        g_Bn[((size_t)b * CH + k) * NCTX + j] = row[np[j]];
}

// ---------------- K4: fp32 GEMM (3-stage cp.async, 1 sync/tile) -------------
#define BM 128
#define BN 128
#define BK 16
#define NT (CH / BK)

__device__ __forceinline__ unsigned ford(float f) {
    unsigned u = __float_as_uint(f);
    return (u & 0x80000000u) ? ~u : (u | 0x80000000u);
}

__device__ __forceinline__ void cp16(void* sdst, const void* gsrc) {
    unsigned saddr = (unsigned)__cvta_generic_to_shared(sdst);
    asm volatile("cp.async.ca.shared.global [%0], [%1], 16;\n" :: "r"(saddr), "l"(gsrc));
}

__global__ void __launch_bounds__(256, 2) k_gemm() {
    __shared__ __align__(16) float As[3][BK][BM];
    __shared__ __align__(16) float Bs[3][BK][BN];

    int b  = blockIdx.z;
    int i0 = blockIdx.y * BM;
    int j0 = blockIdx.x * BN;
    int tid = threadIdx.x;
    int tx = tid & 15, ty = tid >> 4;
    int cA = tx * 4;

    const float* A  = g_Am + (size_t)b * CH * NMASK + i0;
    const float* Bp = g_Bn + (size_t)b * CH * NCTX  + j0;

    unsigned long long acc[8][4];
#pragma unroll
    for (int r = 0; r < 8; r++)
#pragma unroll
        for (int q = 0; q < 4; q++) acc[r][q] = 0ull;

#define COPY_TILE(t, s_)                                                      \
    do {                                                                      \
        const float* ga = A  + (size_t)((t) * BK + ty) * NMASK + cA;          \
        const float* gb = Bp + (size_t)((t) * BK + ty) * NCTX  + cA;          \
        cp16(&As[s_][ty][cA],      ga);                                       \
        cp16(&As[s_][ty][64 + cA], ga + 64);                                  \
        cp16(&Bs[s_][ty][cA],      gb);                                       \
        cp16(&Bs[s_][ty][64 + cA], gb + 64);                                  \
        asm volatile("cp.async.commit_group;\n");                             \
    } while (0)

    COPY_TILE(0, 0);
    COPY_TILE(1, 1);

#pragma unroll 1
    for (int t = 0; t < NT; t++) {
        if (t < NT - 1) asm volatile("cp.async.wait_group 1;\n");
        else            asm volatile("cp.async.wait_group 0;\n");
        __syncthreads();
        // prefetch tile t+2 into slot (t+2)%3 == (t-1)%3 whose readers finished at t-1
        if (t + 2 < NT) { int sp = (t + 2) % 3; COPY_TILE(t + 2, sp); }
        int s = t % 3;
#pragma unroll
        for (int kk = 0; kk < BK; kk++) {
            float4 a0 = *(const float4*)&As[s][kk][ty * 4];
            float4 a1 = *(const float4*)&As[s][kk][64 + ty * 4];
            ulonglong2 bv0 = *(const ulonglong2*)&Bs[s][kk][tx * 4];
            ulonglong2 bv1 = *(const ulonglong2*)&Bs[s][kk][64 + tx * 4];
            float ar[8] = {a0.x, a0.y, a0.z, a0.w, a1.x, a1.y, a1.z, a1.w};
            unsigned long long bq[4] = {bv0.x, bv0.y, bv1.x, bv1.y};
#pragma unroll
            for (int r = 0; r < 8; r++) {
                unsigned long long a2;
                asm("mov.b64 %0, {%1, %1};" : "=l"(a2) : "r"(__float_as_uint(ar[r])));
#pragma unroll
                for (int q = 0; q < 4; q++)
                    asm("fma.rn.f32x2 %0, %1, %2, %0;"
                        : "+l"(acc[r][q]) : "l"(a2), "l"(bq[q]));
            }
        }
    }

    float invc[8];
#pragma unroll
    for (int g = 0; g < 2; g++)
#pragma unroll
        for (int e = 0; e < 4; e++)
            invc[g * 4 + e] = g_invc[b * NCTX + j0 + g * 64 + tx * 4 + e];

#pragma unroll
    for (int r = 0; r < 8; r++) {
        int irow = (r < 4) ? (ty * 4 + r) : (64 + ty * 4 + (r - 4));
        unsigned long long bp = 0ull;
#pragma unroll
        for (int q = 0; q < 4; q++) {
            float lo = __uint_as_float((unsigned)acc[r][q]);
            float hi = __uint_as_float((unsigned)(acc[r][q] >> 32));
            float v0 = lo * invc[q * 2];
            float v1 = hi * invc[q * 2 + 1];
            int jg = j0 + ((q >> 1) * 64) + tx * 4 + (q & 1) * 2;
            unsigned long long p0 = ((unsigned long long)ford(v0) << 32) | (unsigned)(~(unsigned)jg);
            unsigned long long p1 = ((unsigned long long)ford(v1) << 32) | (unsigned)(~(unsigned)(jg + 1));
            if (p0 > bp) bp = p0;
            if (p1 > bp) bp = p1;
        }
#pragma unroll
        for (int o = 1; o < 16; o <<= 1) {
            unsigned long long other = __shfl_xor_sync(0xffffffffu, bp, o);
            if (other > bp) bp = other;
        }
        if (tx == 0) atomicMax(&g_packed[b * NMASK + i0 + irow], bp);
    }
}

// ---------------- K5: finalize pick + gather from L2-hot scratch ------------
__global__ void k_finalize() {
    int i = blockIdx.x;
    int b = blockIdx.y;
    int t = threadIdx.x;  // 256
    __shared__ int s_j;
    __shared__ float s_invm;
    if (t == 0) {
        unsigned long long pk = g_packed[b * NMASK + i];
        unsigned j  = ~(unsigned)pk;
        unsigned ov = (unsigned)(pk >> 32);
        unsigned fb = (ov & 0x80000000u) ? (ov & 0x7fffffffu) : ~ov;
        float val = __uint_as_float(fb);
        float im  = g_invm[b * NMASK + i];
        g_maxc[b * NMASK + i] = val * im;
        s_j = (int)j;
        s_invm = im;
    }
    __syncthreads();
    int jj = s_j;
    float im = s_invm;
    const float* Am = g_Am + (size_t)b * CH * NMASK;
    const float* Bn = g_Bn + (size_t)b * CH * NCTX;
    size_t o = ((size_t)b * NMASK + i) * CH;
#pragma unroll
    for (int c = t; c < CH; c += 256) {
        g_best[o + c] = Bn[(size_t)c * NCTX + jj];
        g_mskn[o + c] = Am[(size_t)c * NMASK + i] * im;
    }
}

// ---------------- K6: warp-specialized scan v2 (decoupled handshake) --------
// warp 0 = consumer: dependent math chain only
// warp 1 = producer: rflag publication leads; writeback+recycle lags by 2
#define NSTAGE 8

__device__ __forceinline__ float frcp(float x) {
    float r;
    asm("rcp.approx.f32 %0, %1;" : "=f"(r) : "f"(x));
    return r;
}
__device__ __forceinline__ float frsq(float x) {
    float r;
    asm("rsqrt.approx.f32 %0, %1;" : "=f"(r) : "f"(x));
    return r;
}
__device__ __forceinline__ void st_release_s32(volatile int* p, int v) {
    unsigned a = (unsigned)__cvta_generic_to_shared((void*)p);
    asm volatile("st.release.cta.shared.b32 [%0], %1;" :: "r"(a), "r"(v) : "memory");
}
__device__ __forceinline__ int ld_acquire_s32(volatile int* p) {
    unsigned a = (unsigned)__cvta_generic_to_shared((void*)p);
    int v;
    asm volatile("ld.acquire.cta.shared.b32 %0, [%1];" : "=r"(v) : "r"(a) : "memory");
    return v;
}

__global__ void __launch_bounds__(64, 1) k_scan() {
    __shared__ __align__(16) float ring[NSTAGE][2][CH];   // 32KB operand ring
    __shared__ __align__(16) float qbuf[NSTAGE][CH];      // 16KB q ring
    __shared__ int rflag[NSTAGE];
    __shared__ int qflag[NSTAGE];

    int b = blockIdx.x;
    int warp = threadIdx.x >> 5;
    int lane = threadIdx.x & 31;

    const float* MN = g_mskn + (size_t)b * NMASK * CH;
    const float* BS = g_best + (size_t)b * NMASK * CH;
    float*       GE = g_gen  + (size_t)b * NMASK * CH;
    const float* MX = g_maxc + b * NMASK;
    size_t lo = (size_t)lane * 16;

    if (threadIdx.x < NSTAGE) { rflag[threadIdx.x] = -1; qflag[threadIdx.x] = -1; }
    __syncthreads();

#define SCAN_PREFETCH(i, s)                                                   \
    do {                                                                      \
        const float* pm = MN + (size_t)(i) * CH + lo;                         \
        const float* pb = BS + (size_t)(i) * CH + lo;                         \
        cp16(&ring[s][0][lo],      pm);                                       \
        cp16(&ring[s][0][lo + 4],  pm + 4);                                   \
        cp16(&ring[s][0][lo + 8],  pm + 8);                                   \
        cp16(&ring[s][0][lo + 12], pm + 12);                                  \
        cp16(&ring[s][1][lo],      pb);                                       \
        cp16(&ring[s][1][lo + 4],  pb + 4);                                   \
        cp16(&ring[s][1][lo + 8],  pb + 8);                                   \
        cp16(&ring[s][1][lo + 12], pb + 12);                                  \
        asm volatile("cp.async.commit_group;\n");                             \
    } while (0)

    if (warp == 1) {
        // ---------------- producer ----------------
#pragma unroll
        for (int s = 0; s < NSTAGE; s++) SCAN_PREFETCH(s, s);   // steps 0..7

#pragma unroll 1
        for (int i = 0; i < NMASK; i++) {
            // (a) lagged writeback + slot recycle for step i-2 (qflag long set)
            if (i >= 2) {
                int sw = (i - 2) & (NSTAGE - 1);
                while (ld_acquire_s32(&qflag[sw]) < i - 2) { }
                float* ge = GE + (size_t)(i - 2) * CH + lo;
#pragma unroll
                for (int u = 0; u < 4; u++)
                    *(float4*)(ge + u * 4) = *(const float4*)&qbuf[sw][lo + u * 4];
                if (i + 6 < NMASK) SCAN_PREFETCH(i + 6, sw);     // (i+6)%8 == (i-2)%8
            }
            // (b) publish readiness of step i (depends only on cp.async groups)
            asm volatile("cp.async.wait_group 6;\n");
            __syncwarp();
            if (lane == 0) st_release_s32(&rflag[i & (NSTAGE - 1)], i);
        }
        // tail writebacks: steps NMASK-2, NMASK-1
#pragma unroll
        for (int i = NMASK - 2; i < NMASK; i++) {
            int sw = i & (NSTAGE - 1);
            while (ld_acquire_s32(&qflag[sw]) < i) { }
            float* ge = GE + (size_t)i * CH + lo;
#pragma unroll
            for (int u = 0; u < 4; u++)
                *(float4*)(ge + u * 4) = *(const float4*)&qbuf[sw][lo + u * 4];
        }
    } else {
        // ---------------- consumer ----------------
        float q[16];
#pragma unroll
        for (int e = 0; e < 16; e++) q[e] = 0.f;
        float mx0 = MX[0];

#pragma unroll 1
        for (int i = 0; i < NMASK; i++) {
            int s = i & (NSTAGE - 1);
            float mx = mx0;
            mx0 = (i + 1 < NMASK) ? MX[i + 1] : 0.f;

            while (ld_acquire_s32(&rflag[s]) < i) { }

            float mn[16], bs[16];
#pragma unroll
            for (int u = 0; u < 4; u++) {
                float4 a = *(const float4*)&ring[s][0][lo + u * 4];
                mn[u * 4 + 0] = a.x; mn[u * 4 + 1] = a.y; mn[u * 4 + 2] = a.z; mn[u * 4 + 3] = a.w;
                float4 c = *(const float4*)&ring[s][1][lo + u * 4];
                bs[u * 4 + 0] = c.x; bs[u * 4 + 1] = c.y; bs[u * 4 + 2] = c.z; bs[u * 4 + 3] = c.w;
            }

            float p1[8], p2[8];
#pragma unroll
            for (int e = 0; e < 8; e++) {
                p1[e] = __fmaf_rn(q[e], q[e], q[e + 8] * q[e + 8]);
                p2[e] = __fmaf_rn(mn[e], q[e], mn[e + 8] * q[e + 8]);
            }
#pragma unroll
            for (int w = 4; w; w >>= 1)
#pragma unroll
                for (int e = 0; e < w; e++) { p1[e] += p1[e + w]; p2[e] += p2[e + w]; }
            float s1 = p1[0], s2 = p2[0];
#pragma unroll
            for (int o = 16; o; o >>= 1) {
                s1 += __shfl_xor_sync(0xffffffffu, s1, o);
                s2 += __shfl_xor_sync(0xffffffffu, s2, o);
            }
            float r   = (s1 > 0.f) ? frsq(s1) : 0.f;
            float nrm = s1 * r;                          // sqrt(s1), 0 if s1==0
            float u   = __fmaf_rn(mx, nrm, mx * EPSF);   // mx*(nrm+eps)
            float s2p = fmaxf(s2, 0.f);
            float T   = __fmaf_rn(EPSF, nrm, s2p + u);
            float rT  = frcp(T);
            float w1 = s2p * rT, w2 = u * rT;
#pragma unroll
            for (int e = 0; e < 16; e++) q[e] = __fmaf_rn(w1, q[e], w2 * bs[e]);

            // publish q: stores -> syncwarp -> release flag (correct order)
#pragma unroll
            for (int u = 0; u < 4; u++) {
                float4 w;
                w.x = q[u * 4 + 0]; w.y = q[u * 4 + 1]; w.z = q[u * 4 + 2]; w.w = q[u * 4 + 3];
                *(float4*)&qbuf[s][lo + u * 4] = w;
            }
            __syncwarp();
            if (lane == 0) st_release_s32(&qflag[s], i);
        }
    }
}

// ---------------- K7: assemble output ---------------------------------------
__global__ void k_out(const float* __restrict__ x, float* __restrict__ out) {
    int idx = blockIdx.x * 256 + threadIdx.x;
    int p = idx & (HW - 1);
    int c = (idx >> 12) & (CH - 1);
    int b = idx >> 21;
    int mi = g_imask[p];
    float v = (mi >= 0) ? g_gen[(((size_t)b * NMASK) + mi) * CH + c] : x[idx];
    out[idx] = v;
}

// ---------------- launch -----------------------------------------------------
extern "C" void kernel_launch(void* const* d_in, const int* in_sizes, int n_in,
                              void* d_out, int out_size) {
    const float* x  = (const float*)d_in[0];
    const int*   np = (const int*)d_in[2];
    const int*   mp = (const int*)d_in[3];
    float*       out = (float*)d_out;

    k_part    <<<dim3(HW / 256, BATCH, NSPLIT), 256>>>(x);
    k_invall  <<<BATCH * HW / 256, 256>>>();
    k_setup   <<<1, 1024>>>(np, mp);
    k_gather  <<<dim3(CH, BATCH), 1024>>>(x, np, mp);
    k_gemm    <<<dim3(NCTX / BN, NMASK / BM, BATCH), 256>>>();
    k_finalize<<<dim3(NMASK, BATCH), 256>>>();
    k_scan    <<<BATCH, 64>>>();
    k_out     <<<(BATCH * CH * HW) / 256, 256>>>(x, out);
}

// round 8
// speedup vs baseline: 1.2702x; 1.0563x over previous
#include <cuda_runtime.h>

#define BATCH 8
#define CH    512
#define HW    4096
#define NMASK 1024
#define NCTX  3072
#define EPSF  1e-8f
#define NSPLIT 4

// ---------------- scratch (static __device__ globals; no allocation) ----------
__device__ float g_Am[BATCH * CH * NMASK];            // A gathered [b][k][i]
__device__ float g_Bn[BATCH * CH * NCTX];             // B gathered [b][k][j]
__device__ float g_best[BATCH * NMASK * CH];
__device__ float g_mskn[BATCH * NMASK * CH];
__device__ float g_gen[BATCH * NMASK * CH];
__device__ float g_part[NSPLIT][BATCH * HW];
__device__ float g_invall[BATCH * HW];
__device__ float g_invc[BATCH * NCTX];
__device__ float g_invm[BATCH * NMASK];
__device__ float g_maxc[BATCH * NMASK];
__device__ unsigned long long g_packed[BATCH * NMASK];
__device__ int   g_imask[HW];

// ---------------- K1a: partial column norms ---------------------------------
__global__ void k_part(const float* __restrict__ x) {
    int p = blockIdx.x * 256 + threadIdx.x;
    int b = blockIdx.y;
    int z = blockIdx.z;
    const float* base = x + ((size_t)b * CH + (size_t)z * (CH / NSPLIT)) * HW + p;
    float s = 0.f;
#pragma unroll 8
    for (int c = 0; c < CH / NSPLIT; c++) {
        float v = base[(size_t)c * HW];
        s += v * v;
    }
    g_part[z][b * HW + p] = s;
}

// ---------------- K1b: combine partials -> invall ---------------------------
__global__ void k_invall() {
    int i = blockIdx.x * 256 + threadIdx.x;
    float s = g_part[0][i] + g_part[1][i] + g_part[2][i] + g_part[3][i];
    g_invall[i] = 1.f / (sqrtf(s) + EPSF);
}

// ---------------- K2: setup --------------------------------------------------
__global__ void k_setup(const int* __restrict__ np, const int* __restrict__ mp) {
    int t = threadIdx.x;  // 1024 threads, 1 block
    for (int p = t; p < HW; p += 1024) g_imask[p] = -1;
    __syncthreads();
    g_imask[mp[t]] = t;
    for (int i = t; i < BATCH * NMASK; i += 1024) g_packed[i] = 0ull;
    for (int i = t; i < BATCH * NMASK; i += 1024) {
        int b = i / NMASK;
        g_invm[i] = g_invall[b * HW + mp[i % NMASK]];
    }
    for (int j = t; j < BATCH * NCTX; j += 1024) {
        int b = j / NCTX;
        g_invc[j] = g_invall[b * HW + np[j % NCTX]];
    }
}

// ---------------- K3: gather A (mask cols) and B (ctx cols), K-major --------
__global__ void k_gather(const float* __restrict__ x,
                         const int* __restrict__ np, const int* __restrict__ mp) {
    int k = blockIdx.x;
    int b = blockIdx.y;
    int t = threadIdx.x;        // 1024
    const float* row = x + ((size_t)b * CH + k) * HW;
    g_Am[((size_t)b * CH + k) * NMASK + t] = row[mp[t]];
#pragma unroll
    for (int j = t; j < NCTX; j += 1024)
        g_Bn[((size_t)b * CH + k) * NCTX + j] = row[np[j]];
}

// ---------------- K4: fp32 GEMM (2-stage cp.async, f32x2 FFMA) --------------
#define BM 128
#define BN 128
#define BK 16
#define NT (CH / BK)

__device__ __forceinline__ unsigned ford(float f) {
    unsigned u = __float_as_uint(f);
    return (u & 0x80000000u) ? ~u : (u | 0x80000000u);
}

__device__ __forceinline__ void cp16(void* sdst, const void* gsrc) {
    unsigned saddr = (unsigned)__cvta_generic_to_shared(sdst);
    asm volatile("cp.async.ca.shared.global [%0], [%1], 16;\n" :: "r"(saddr), "l"(gsrc));
}

__global__ void __launch_bounds__(256, 2) k_gemm() {
    __shared__ __align__(16) float As[2][BK][BM];
    __shared__ __align__(16) float Bs[2][BK][BN];

    int b  = blockIdx.z;
    int i0 = blockIdx.y * BM;
    int j0 = blockIdx.x * BN;
    int tid = threadIdx.x;
    int tx = tid & 15, ty = tid >> 4;
    int cA = tx * 4;

    const float* A  = g_Am + (size_t)b * CH * NMASK + i0;
    const float* Bp = g_Bn + (size_t)b * CH * NCTX  + j0;

    unsigned long long acc[8][4];
#pragma unroll
    for (int r = 0; r < 8; r++)
#pragma unroll
        for (int q = 0; q < 4; q++) acc[r][q] = 0ull;

#define COPY_TILE(t)                                                          \
    do {                                                                      \
        int s_ = (t) & 1;                                                     \
        const float* ga = A  + (size_t)((t) * BK + ty) * NMASK + cA;          \
        const float* gb = Bp + (size_t)((t) * BK + ty) * NCTX  + cA;          \
        cp16(&As[s_][ty][cA],      ga);                                       \
        cp16(&As[s_][ty][64 + cA], ga + 64);                                  \
        cp16(&Bs[s_][ty][cA],      gb);                                       \
        cp16(&Bs[s_][ty][64 + cA], gb + 64);                                  \
        asm volatile("cp.async.commit_group;\n");                             \
    } while (0)

    COPY_TILE(0);
    COPY_TILE(1);

#pragma unroll 1
    for (int t = 0; t < NT; t++) {
        if (t < NT - 1) asm volatile("cp.async.wait_group 1;\n");
        else            asm volatile("cp.async.wait_group 0;\n");
        __syncthreads();
        int s = t & 1;
#pragma unroll
        for (int kk = 0; kk < BK; kk++) {
            float4 a0 = *(const float4*)&As[s][kk][ty * 4];
            float4 a1 = *(const float4*)&As[s][kk][64 + ty * 4];
            ulonglong2 bv0 = *(const ulonglong2*)&Bs[s][kk][tx * 4];
            ulonglong2 bv1 = *(const ulonglong2*)&Bs[s][kk][64 + tx * 4];
            float ar[8] = {a0.x, a0.y, a0.z, a0.w, a1.x, a1.y, a1.z, a1.w};
            unsigned long long bq[4] = {bv0.x, bv0.y, bv1.x, bv1.y};
#pragma unroll
            for (int r = 0; r < 8; r++) {
                unsigned long long a2;
                asm("mov.b64 %0, {%1, %1};" : "=l"(a2) : "r"(__float_as_uint(ar[r])));
#pragma unroll
                for (int q = 0; q < 4; q++)
                    asm("fma.rn.f32x2 %0, %1, %2, %0;"
                        : "+l"(acc[r][q]) : "l"(a2), "l"(bq[q]));
            }
        }
        __syncthreads();
        if (t + 2 < NT) COPY_TILE(t + 2);
    }

    float invc[8];
#pragma unroll
    for (int g = 0; g < 2; g++)
#pragma unroll
        for (int e = 0; e < 4; e++)
            invc[g * 4 + e] = g_invc[b * NCTX + j0 + g * 64 + tx * 4 + e];

#pragma unroll
    for (int r = 0; r < 8; r++) {
        int irow = (r < 4) ? (ty * 4 + r) : (64 + ty * 4 + (r - 4));
        unsigned long long bp = 0ull;
#pragma unroll
        for (int q = 0; q < 4; q++) {
            float lo = __uint_as_float((unsigned)acc[r][q]);
            float hi = __uint_as_float((unsigned)(acc[r][q] >> 32));
            float v0 = lo * invc[q * 2];
            float v1 = hi * invc[q * 2 + 1];
            int jg = j0 + ((q >> 1) * 64) + tx * 4 + (q & 1) * 2;
            unsigned long long p0 = ((unsigned long long)ford(v0) << 32) | (unsigned)(~(unsigned)jg);
            unsigned long long p1 = ((unsigned long long)ford(v1) << 32) | (unsigned)(~(unsigned)(jg + 1));
            if (p0 > bp) bp = p0;
            if (p1 > bp) bp = p1;
        }
#pragma unroll
        for (int o = 1; o < 16; o <<= 1) {
            unsigned long long other = __shfl_xor_sync(0xffffffffu, bp, o);
            if (other > bp) bp = other;
        }
        if (tx == 0) atomicMax(&g_packed[b * NMASK + i0 + irow], bp);
    }
}

// ---------------- K5: finalize pick + gather from L2-hot scratch ------------
__global__ void k_finalize() {
    int i = blockIdx.x;
    int b = blockIdx.y;
    int t = threadIdx.x;  // 256
    __shared__ int s_j;
    __shared__ float s_invm;
    if (t == 0) {
        unsigned long long pk = g_packed[b * NMASK + i];
        unsigned j  = ~(unsigned)pk;
        unsigned ov = (unsigned)(pk >> 32);
        unsigned fb = (ov & 0x80000000u) ? (ov & 0x7fffffffu) : ~ov;
        float val = __uint_as_float(fb);
        float im  = g_invm[b * NMASK + i];
        g_maxc[b * NMASK + i] = val * im;
        s_j = (int)j;
        s_invm = im;
    }
    __syncthreads();
    int jj = s_j;
    float im = s_invm;
    const float* Am = g_Am + (size_t)b * CH * NMASK;
    const float* Bn = g_Bn + (size_t)b * CH * NCTX;
    size_t o = ((size_t)b * NMASK + i) * CH;
#pragma unroll
    for (int c = t; c < CH; c += 256) {
        g_best[o + c] = Bn[(size_t)c * NCTX + jj];
        g_mskn[o + c] = Am[(size_t)c * NMASK + i] * im;
    }
}

// ---------------- K6: scan v3 — leading producer, consumer-owned writeback --
// warp 0 = consumer: math chain + GE STG, releases cflag after LDS
// warp 1 = producer: publishes rflag[i] FIRST, then lag-2 slot recycle
#define NSTAGE 8

__device__ __forceinline__ float frcp(float x) {
    float r;
    asm("rcp.approx.f32 %0, %1;" : "=f"(r) : "f"(x));
    return r;
}
__device__ __forceinline__ float frsq(float x) {
    float r;
    asm("rsqrt.approx.f32 %0, %1;" : "=f"(r) : "f"(x));
    return r;
}
__device__ __forceinline__ void st_release_s32(volatile int* p, int v) {
    unsigned a = (unsigned)__cvta_generic_to_shared((void*)p);
    asm volatile("st.release.cta.shared.b32 [%0], %1;" :: "r"(a), "r"(v) : "memory");
}
__device__ __forceinline__ int ld_acquire_s32(volatile int* p) {
    unsigned a = (unsigned)__cvta_generic_to_shared((void*)p);
    int v;
    asm volatile("ld.acquire.cta.shared.b32 %0, [%1];" : "=r"(v) : "r"(a) : "memory");
    return v;
}

__global__ void __launch_bounds__(64, 1) k_scan() {
    __shared__ __align__(16) float ring[NSTAGE][2][CH];   // 32KB operand ring
    __shared__ int rflag[NSTAGE];    // producer: step whose data is ready in slot
    __shared__ int cflag[NSTAGE];    // consumer: step whose LDS from slot is done

    int b = blockIdx.x;
    int warp = threadIdx.x >> 5;
    int lane = threadIdx.x & 31;

    const float* MN = g_mskn + (size_t)b * NMASK * CH;
    const float* BS = g_best + (size_t)b * NMASK * CH;
    float*       GE = g_gen  + (size_t)b * NMASK * CH;
    const float* MX = g_maxc + b * NMASK;
    size_t lo = (size_t)lane * 16;

    if (threadIdx.x < NSTAGE) { rflag[threadIdx.x] = -1; cflag[threadIdx.x] = -1; }
    __syncthreads();

#define SCAN_PREFETCH(i, s)                                                   \
    do {                                                                      \
        const float* pm = MN + (size_t)(i) * CH + lo;                         \
        const float* pb = BS + (size_t)(i) * CH + lo;                         \
        cp16(&ring[s][0][lo],      pm);                                       \
        cp16(&ring[s][0][lo + 4],  pm + 4);                                   \
        cp16(&ring[s][0][lo + 8],  pm + 8);                                   \
        cp16(&ring[s][0][lo + 12], pm + 12);                                  \
        cp16(&ring[s][1][lo],      pb);                                       \
        cp16(&ring[s][1][lo + 4],  pb + 4);                                   \
        cp16(&ring[s][1][lo + 8],  pb + 8);                                   \
        cp16(&ring[s][1][lo + 12], pb + 12);                                  \
        asm volatile("cp.async.commit_group;\n");                             \
    } while (0)

    if (warp == 1) {
        // ---------------- producer ----------------
#pragma unroll
        for (int s = 0; s < NSTAGE; s++) SCAN_PREFETCH(s, s);   // steps 0..7

        // main loop: publish rflag[i] first (group math: issued = i+6 at this
        // point, wait(5) => retired >= i+1 => step i landed), then lag-2 recycle.
#pragma unroll 1
        for (int i = 0; i < NMASK - 6; i++) {
            asm volatile("cp.async.wait_group 5;\n");
            __syncwarp();
            if (lane == 0) st_release_s32(&rflag[i & (NSTAGE - 1)], i);
            if (i >= 2) {
                int step = i + 6;                 // <= NMASK-1 in this range
                int sw = step & (NSTAGE - 1);     // == (i-2)&7
                while (ld_acquire_s32(&cflag[sw]) < i - 2) { }
                SCAN_PREFETCH(step, sw);
            }
        }
        // tail: all groups issued; drain and publish the last 6 steps
        asm volatile("cp.async.wait_group 0;\n");
        __syncwarp();
        if (lane == 0) {
#pragma unroll
            for (int k = NMASK - 6; k < NMASK; k++)
                st_release_s32(&rflag[k & (NSTAGE - 1)], k);
        }
    } else {
        // ---------------- consumer ----------------
        float q[16];
#pragma unroll
        for (int e = 0; e < 16; e++) q[e] = 0.f;
        float mx0 = MX[0];

#pragma unroll 1
        for (int i = 0; i < NMASK; i++) {
            int s = i & (NSTAGE - 1);
            float mx = mx0;
            mx0 = (i + 1 < NMASK) ? MX[i + 1] : 0.f;

            while (ld_acquire_s32(&rflag[s]) < i) { }

            float mn[16], bs[16];
#pragma unroll
            for (int u = 0; u < 4; u++) {
                float4 a = *(const float4*)&ring[s][0][lo + u * 4];
                mn[u * 4 + 0] = a.x; mn[u * 4 + 1] = a.y; mn[u * 4 + 2] = a.z; mn[u * 4 + 3] = a.w;
                float4 c = *(const float4*)&ring[s][1][lo + u * 4];
                bs[u * 4 + 0] = c.x; bs[u * 4 + 1] = c.y; bs[u * 4 + 2] = c.z; bs[u * 4 + 3] = c.w;
            }
            // slot consumed: free it for the producer (release orders the LDS above)
            __syncwarp();
            if (lane == 0) st_release_s32(&cflag[s], i);

            float p1[8], p2[8];
#pragma unroll
            for (int e = 0; e < 8; e++) {
                p1[e] = __fmaf_rn(q[e], q[e], q[e + 8] * q[e + 8]);
                p2[e] = __fmaf_rn(mn[e], q[e], mn[e + 8] * q[e + 8]);
            }
#pragma unroll
            for (int w = 4; w; w >>= 1)
#pragma unroll
                for (int e = 0; e < w; e++) { p1[e] += p1[e + w]; p2[e] += p2[e + w]; }
            float s1 = p1[0], s2 = p2[0];
#pragma unroll
            for (int o = 16; o; o >>= 1) {
                s1 += __shfl_xor_sync(0xffffffffu, s1, o);
                s2 += __shfl_xor_sync(0xffffffffu, s2, o);
            }
            float r   = (s1 > 0.f) ? frsq(s1) : 0.f;
            float nrm = s1 * r;                          // sqrt(s1), 0 if s1==0
            float u   = __fmaf_rn(mx, nrm, mx * EPSF);   // mx*(nrm+eps)
            float s2p = fmaxf(s2, 0.f);
            float T   = __fmaf_rn(EPSF, nrm, s2p + u);
            float rT  = frcp(T);
            float w1 = s2p * rT, w2 = u * rT;
#pragma unroll
            for (int e = 0; e < 16; e++) q[e] = __fmaf_rn(w1, q[e], w2 * bs[e]);

            float* ge = GE + (size_t)i * CH + lo;
#pragma unroll
            for (int u = 0; u < 4; u++) {
                float4 w;
                w.x = q[u * 4 + 0]; w.y = q[u * 4 + 1]; w.z = q[u * 4 + 2]; w.w = q[u * 4 + 3];
                *(float4*)(ge + u * 4) = w;
            }
        }
    }
}

// ---------------- K7: assemble output ---------------------------------------
__global__ void k_out(const float* __restrict__ x, float* __restrict__ out) {
    int idx = blockIdx.x * 256 + threadIdx.x;
    int p = idx & (HW - 1);
    int c = (idx >> 12) & (CH - 1);
    int b = idx >> 21;
    int mi = g_imask[p];
    float v = (mi >= 0) ? g_gen[(((size_t)b * NMASK) + mi) * CH + c] : x[idx];
    out[idx] = v;
}

// ---------------- launch -----------------------------------------------------
extern "C" void kernel_launch(void* const* d_in, const int* in_sizes, int n_in,
                              void* d_out, int out_size) {
    const float* x  = (const float*)d_in[0];
    const int*   np = (const int*)d_in[2];
    const int*   mp = (const int*)d_in[3];
    float*       out = (float*)d_out;

    k_part    <<<dim3(HW / 256, BATCH, NSPLIT), 256>>>(x);
    k_invall  <<<BATCH * HW / 256, 256>>>();
    k_setup   <<<1, 1024>>>(np, mp);
    k_gather  <<<dim3(CH, BATCH), 1024>>>(x, np, mp);
    k_gemm    <<<dim3(NCTX / BN, NMASK / BM, BATCH), 256>>>();
    k_finalize<<<dim3(NMASK, BATCH), 256>>>();
    k_scan    <<<BATCH, 64>>>();
    k_out     <<<(BATCH * CH * HW) / 256, 256>>>(x, out);
}